// round 9
// baseline (speedup 1.0000x reference)
#include <cuda_runtime.h>
#include <cuda_fp16.h>
#include <float.h>

// ---------------------------------------------------------------------------
// Problem constants
// ---------------------------------------------------------------------------
#define Bn     16
#define Hn     16
#define DHn    64
#define NTOK   1280          // padded sequence (SEQ_LEN + 1)
#define NREAL  1279          // real tokens
#define DIMn   1024
#define TXT    256           // text length
#define BH     256           // Bn * Hn
#define HD     (NTOK * DHn)  // 81920 halfs per (b,h) plane
#define MQKV   (Bn * NTOK)   // 20480
#define MOUT   (Bn * NREAL)  // 20464
#define QSCALE 0.125f        // DH^-0.5

// ---------------------------------------------------------------------------
// Scratch (device globals: allocation-free)
// ---------------------------------------------------------------------------
__device__ __half g_qh[(size_t)BH * HD];
__device__ __half g_kh[(size_t)BH * HD];
__device__ __half g_vh[(size_t)BH * HD];
__device__ __half g_xh[(size_t)MQKV * DIMn];     // padded x in fp16
__device__ __half g_wqkvh[3 * DIMn * DIMn];      // w_qkv fp16
__device__ __half g_wouth[DIMn * DIMn];          // w_out fp16
__device__ __half g_oh[(size_t)MOUT * DIMn];     // attn out, de-interleaved fp16

// ---------------------------------------------------------------------------
// MMA / ldmatrix helpers
// ---------------------------------------------------------------------------
__device__ __forceinline__ void mma_f16(float c[4], const unsigned a[4],
                                        const unsigned b[2]) {
    asm volatile(
        "mma.sync.aligned.m16n8k16.row.col.f32.f16.f16.f32 "
        "{%0,%1,%2,%3}, {%4,%5,%6,%7}, {%8,%9}, {%0,%1,%2,%3};\n"
        : "+f"(c[0]), "+f"(c[1]), "+f"(c[2]), "+f"(c[3])
        : "r"(a[0]), "r"(a[1]), "r"(a[2]), "r"(a[3]), "r"(b[0]), "r"(b[1]));
}
__device__ __forceinline__ void ldsm4(unsigned& r0, unsigned& r1,
                                      unsigned& r2, unsigned& r3, unsigned addr) {
    asm volatile("ldmatrix.sync.aligned.m8n8.x4.shared.b16 {%0,%1,%2,%3}, [%4];\n"
                 : "=r"(r0), "=r"(r1), "=r"(r2), "=r"(r3) : "r"(addr));
}
__device__ __forceinline__ void ldsm4t(unsigned& r0, unsigned& r1,
                                       unsigned& r2, unsigned& r3, unsigned addr) {
    asm volatile("ldmatrix.sync.aligned.m8n8.x4.trans.shared.b16 {%0,%1,%2,%3}, [%4];\n"
                 : "=r"(r0), "=r"(r1), "=r"(r2), "=r"(r3) : "r"(addr));
}

// GEMM smem swizzle: 64B rows (32 halfs), chunk c (0..3)
__device__ __forceinline__ unsigned swz(int row, int c) {
    return (unsigned)(row * 64 + ((c ^ ((row >> 1) & 3)) << 4));
}
// Attention tiles: 128B rows (64 halfs), chunk c (0..7)
__device__ __forceinline__ unsigned off16(int row, int c) {
    return (unsigned)(row * 128 + ((c ^ (row & 7)) << 4));
}
// Score matrix S: 640B rows (320 halfs), chunk swizzle within 8-chunk groups
__device__ __forceinline__ unsigned sidx16(int row, int c) {
    int cc = (c & ~7) | ((c & 7) ^ (row & 7));
    return (unsigned)(row * 640 + (cc << 4));
}
__device__ __forceinline__ char* sptr(char* base, int row, int col) {
    return base + sidx16(row, col >> 3) + (col & 7) * 2;
}

__device__ __forceinline__ void cp16(unsigned dst, const void* src, bool v) {
    int sz = v ? 16 : 0;
    asm volatile("cp.async.cg.shared.global [%0], [%1], 16, %2;\n"
                 :: "r"(dst), "l"(src), "r"(sz) : "memory");
}
__device__ __forceinline__ void cp_commit() {
    asm volatile("cp.async.commit_group;\n" ::: "memory");
}
__device__ __forceinline__ void cp_wait2() {
    asm volatile("cp.async.wait_group 2;\n" ::: "memory");
}
__device__ __forceinline__ void cp_wait1() {
    asm volatile("cp.async.wait_group 1;\n" ::: "memory");
}

// ---------------------------------------------------------------------------
// fp16 HGEMM, widened: CTA tile 128(M) x 256(N), BK=32, 8 warps as 2x4,
// warp tile 64x64 (4x8 m16n8k16). 4-stage cp.async pipeline (96KB smem),
// 1 CTA/SM (regs ~200). fp32 accumulate.
// EPI=0: scatter fp16 to g_qh/g_kh/g_vh head layout (Q scaled).
// EPI=1: fp32 out + bias.
// smem stage: A 128x32 half (8192 B) @ +0, B 256x32 half (16384 B) @ +8192.
// ---------------------------------------------------------------------------
#define HG_STG  24576
#define HG_SMEM (4 * HG_STG)

template <int EPI>
__global__ __launch_bounds__(256, 1) void hgemm_kernel(
    const __half* __restrict__ A, const __half* __restrict__ B,
    const float* __restrict__ bias, float* __restrict__ out, int Mv)
{
    extern __shared__ __align__(16) __half gsm[];
    const unsigned smbase = (unsigned)__cvta_generic_to_shared(gsm);

    const int tid = threadIdx.x;
    const int m0 = blockIdx.y * 128;
    const int n0 = blockIdx.x * 256;

    // loader mapping: ids 0..511 -> A (row=id>>2, c=id&3);
    //                 ids 512..1535 -> B (row=(id-512)>>2, c=(id-512)&3)
    const int arow0 = tid >> 2, ac0 = tid & 3;                 // r = 0
    const int arow1 = (tid + 256) >> 2, ac1 = tid & 3;         // r = 1
    const bool av0 = (m0 + arow0) < Mv;
    const bool av1 = (m0 + arow1) < Mv;
    const __half* gA0 = A + (size_t)(m0 + arow0) * DIMn + ac0 * 8;
    const __half* gA1 = A + (size_t)(m0 + arow1) * DIMn + ac1 * 8;
    const unsigned dA0 = swz(arow0, ac0), dA1 = swz(arow1, ac1);

    auto load_stage = [&](int s, int k0) {
        const unsigned sa = smbase + s * HG_STG;
        cp16(sa + dA0, gA0 + k0, av0);
        cp16(sa + dA1, gA1 + k0, av1);
#pragma unroll
        for (int r = 2; r < 6; r++) {
            const int idx = tid + 256 * r - 512;
            const int row = idx >> 2, c = idx & 3;
            cp16(sa + 8192 + swz(row, c),
                 B + (size_t)(n0 + row) * DIMn + k0 + c * 8, true);
        }
    };

    const int lane = tid & 31, warp = tid >> 5;
    const int wM = warp >> 2, wN = warp & 3;           // 2 x 4 warps
    const int aRow = wM * 64 + (lane & 15);
    const int aCb  = lane >> 4;
    const int bRow = wN * 64 + (lane & 7) + ((lane >> 4) & 1) * 8;
    const int bCb  = (lane >> 3) & 1;

    float c[4][8][4];
#pragma unroll
    for (int tm = 0; tm < 4; tm++)
#pragma unroll
        for (int tn = 0; tn < 8; tn++)
#pragma unroll
            for (int i = 0; i < 4; i++) c[tm][tn][i] = 0.f;

    load_stage(0, 0);  cp_commit();
    load_stage(1, 32); cp_commit();
    load_stage(2, 64); cp_commit();

#pragma unroll 1
    for (int it = 0; it < 32; it++) {
        cp_wait2();
        __syncthreads();
        const unsigned sb = smbase + (it & 3) * HG_STG;
        const unsigned sbB = sb + 8192;

        unsigned a0[4][4], a1[4][4], b[4][4];
#pragma unroll
        for (int tm = 0; tm < 4; tm++) {
            ldsm4(a0[tm][0], a0[tm][1], a0[tm][2], a0[tm][3],
                  sb + swz(aRow + tm * 16, aCb));
            ldsm4(a1[tm][0], a1[tm][1], a1[tm][2], a1[tm][3],
                  sb + swz(aRow + tm * 16, aCb + 2));
        }
#pragma unroll
        for (int p = 0; p < 4; p++)
            ldsm4(b[p][0], b[p][1], b[p][2], b[p][3],
                  sbB + swz(bRow + p * 16, bCb));

        if (it + 3 < 32) load_stage((it + 3) & 3, (it + 3) * 32);
        cp_commit();

        // mma k16 = 0
#pragma unroll
        for (int tm = 0; tm < 4; tm++)
#pragma unroll
            for (int tn = 0; tn < 8; tn++)
                mma_f16(c[tm][tn], a0[tm], &b[tn >> 1][(tn & 1) * 2]);

        // B fragments k16 = 1 (overlap with k16=0 mma drain)
#pragma unroll
        for (int p = 0; p < 4; p++)
            ldsm4(b[p][0], b[p][1], b[p][2], b[p][3],
                  sbB + swz(bRow + p * 16, bCb + 2));
#pragma unroll
        for (int tm = 0; tm < 4; tm++)
#pragma unroll
            for (int tn = 0; tn < 8; tn++)
                mma_f16(c[tm][tn], a1[tm], &b[tn >> 1][(tn & 1) * 2]);
    }

    const int grp = lane >> 2, qd = lane & 3;
#pragma unroll
    for (int tm = 0; tm < 4; tm++) {
#pragma unroll
        for (int hf = 0; hf < 2; hf++) {
            const int mrow = m0 + wM * 64 + tm * 16 + grp + hf * 8;
            if (EPI == 0) {
                const int b_ = mrow / NTOK;
                const int n_ = mrow - b_ * NTOK;
#pragma unroll
                for (int tn = 0; tn < 8; tn++) {
                    const int col = n0 + wN * 64 + tn * 8 + qd * 2;
                    const int which = col >> 10;
                    const int cc = col & 1023;
                    const int h = cc >> 6;
                    const int d = cc & 63;
                    __half* dst = (which == 0) ? g_qh : ((which == 1) ? g_kh : g_vh);
                    const float sc = (which == 0) ? QSCALE : 1.0f;
                    __half2 hv = __floats2half2_rn(c[tm][tn][hf * 2 + 0] * sc,
                                                   c[tm][tn][hf * 2 + 1] * sc);
                    *(unsigned*)(dst + ((size_t)(b_ * Hn + h) * NTOK + n_) * DHn + d) =
                        *(unsigned*)&hv;
                }
            } else {
                if (mrow < Mv) {
#pragma unroll
                    for (int tn = 0; tn < 8; tn++) {
                        const int col = n0 + wN * 64 + tn * 8 + qd * 2;
                        float2 bb = *(const float2*)(bias + col);
                        float2 v;
                        v.x = c[tm][tn][hf * 2 + 0] + bb.x;
                        v.y = c[tm][tn][hf * 2 + 1] + bb.y;
                        *(float2*)(out + (size_t)mrow * DIMn + col) = v;
                    }
                }
            }
        }
    }
}

// ---------------------------------------------------------------------------
// Merged fp32 -> fp16 conversion kernel (x pad + w_qkv + w_out)
// ---------------------------------------------------------------------------
#define X_E4  (MQKV * DIMn / 4)
#define WQ_E4 (3 * DIMn * DIMn / 4)
#define WO_E4 (DIMn * DIMn / 4)
#define CVT_TOT (X_E4 + WQ_E4 + WO_E4)

__global__ __launch_bounds__(256) void cvt_all_kernel(
    const float* __restrict__ x, const float* __restrict__ wqkv,
    const float* __restrict__ wout)
{
    long i = (long)blockIdx.x * 256 + threadIdx.x;
    if (i >= CVT_TOT) return;
    float4 v;
    __half* dst;
    size_t e;
    if (i < X_E4) {
        e = (size_t)i * 4;
        int m = (int)(e >> 10);
        int col = (int)(e & 1023);
        int b = m / NTOK, n = m - b * NTOK;
        v = make_float4(0.f, 0.f, 0.f, 0.f);
        if (n < NREAL) v = *(const float4*)(x + ((size_t)b * NREAL + n) * DIMn + col);
        dst = g_xh;
    } else if (i < X_E4 + WQ_E4) {
        e = (size_t)(i - X_E4) * 4;
        v = *(const float4*)(wqkv + e);
        dst = g_wqkvh;
    } else {
        e = (size_t)(i - X_E4 - WQ_E4) * 4;
        v = *(const float4*)(wout + e);
        dst = g_wouth;
    }
    __half2 h0 = __floats2half2_rn(v.x, v.y);
    __half2 h1 = __floats2half2_rn(v.z, v.w);
    uint2 u;
    u.x = *(unsigned*)&h0;
    u.y = *(unsigned*)&h1;
    *(uint2*)(dst + e) = u;
}

// ---------------------------------------------------------------------------
// Fused tensor-core attention (unchanged from R8; measured win).
// ---------------------------------------------------------------------------
#define ATT_QOFF 0
#define ATT_B0   8192
#define ATT_B1   16384
#define ATT_SOFF 24576
#define ATT_IOFF 65536
#define ATT_SMEM 65792

__device__ __forceinline__ void att_cp_tile(unsigned dstbase, const __half* g,
                                            int tid) {
#pragma unroll
    for (int r = 0; r < 4; r++) {
        int id = tid + 128 * r;
        int row = id >> 3, c = id & 7;
        cp16(dstbase + off16(row, c), g + row * 64 + c * 8, true);
    }
}

__global__ __launch_bounds__(128) void attn_fused_kernel()
{
    extern __shared__ char sm[];
    const unsigned sb = (unsigned)__cvta_generic_to_shared(sm);
    float* invs = (float*)(sm + ATT_IOFF);

    const int bh = blockIdx.y;
    const int bx = blockIdx.x;
    const bool isText = (bx < 4);
    const int tid = threadIdx.x, lane = tid & 31, warp = tid >> 5;
    const int grp = lane >> 2, qd = lane & 3;

    const int qtok0 = isText ? bx * 64 : TXT + (bx - 4) * 64;

    const __half* qg = g_qh + (size_t)bh * HD + (size_t)qtok0 * DHn;
    const __half* kg = g_kh + (size_t)bh * HD;
    const __half* vg = g_vh + (size_t)bh * HD;

    const int nK = isText ? (bx + 1) : 5;
    const int total = 2 * nK;
    const int ncols = isText ? (qtok0 + 64) : (TXT + 32);

    auto tile_src = [&](int t) -> const __half* {
        if (t < nK) {
            if (isText || t < 4) return kg + (size_t)t * 64 * DHn;
            return kg + (size_t)qtok0 * DHn;
        }
        int v = t - nK;
        if (isText || v < 4) return vg + (size_t)v * 64 * DHn;
        return vg + (size_t)qtok0 * DHn;
    };

    att_cp_tile(sb + ATT_QOFF, qg, tid);
    att_cp_tile(sb + ATT_B0, tile_src(0), tid);
    cp_commit();
    att_cp_tile(sb + ATT_B1, tile_src(1), tid);
    cp_commit();

    const int aRow = warp * 16 + (lane & 15);
    const int aC   = lane >> 4;
    const int bRow = (lane & 7) + ((lane >> 4) & 1) * 8;
    const int bC   = (lane >> 3) & 1;
    const int kb   = (warp >> 1) * 32;

    float co[8][4];
#pragma unroll
    for (int tn = 0; tn < 8; tn++)
#pragma unroll
        for (int i = 0; i < 4; i++) co[tn][i] = 0.f;

#pragma unroll 1
    for (int t = 0; t < total; t++) {
        cp_wait1();
        __syncthreads();

        if (t == nK) {
            const int row = tid >> 1, hv = tid & 1;
            const int half = ncols >> 1;
            const int c0 = hv * half, c1 = c0 + half;
            float mx = -FLT_MAX;
            for (int col = c0; col < c1; col++)
                mx = fmaxf(mx, __half2float(*(__half*)sptr(sm + ATT_SOFF, row, col)));
            mx = fmaxf(mx, __shfl_xor_sync(0xffffffffu, mx, 1));
            float sum = 0.f;
            for (int col = c0; col < c1; col++) {
                char* p = sptr(sm + ATT_SOFF, row, col);
                float e = __expf(__half2float(*(__half*)p) - mx);
                *(__half*)p = __float2half(e);
                sum += e;
            }
            sum += __shfl_xor_sync(0xffffffffu, sum, 1);
            if (hv == 0) invs[row] = 1.f / sum;
            __syncthreads();
        }

        const unsigned kvb = sb + ((t & 1) ? ATT_B1 : ATT_B0);

        if (t < nK) {
            const bool imgTile = (!isText) && (t == 4);
            if (!imgTile) {
                const int j0 = t * 64;
                float cs[8][4];
#pragma unroll
                for (int tn = 0; tn < 8; tn++)
#pragma unroll
                    for (int i = 0; i < 4; i++) cs[tn][i] = 0.f;
#pragma unroll
                for (int k16 = 0; k16 < 4; k16++) {
                    unsigned a[4], b[4][4];
                    ldsm4(a[0], a[1], a[2], a[3],
                          sb + ATT_QOFF + off16(aRow, k16 * 2 + aC));
#pragma unroll
                    for (int p = 0; p < 4; p++)
                        ldsm4(b[p][0], b[p][1], b[p][2], b[p][3],
                              kvb + off16(p * 16 + bRow, k16 * 2 + bC));
#pragma unroll
                    for (int tn = 0; tn < 8; tn++)
                        mma_f16(cs[tn], a, &b[tn >> 1][(tn & 1) * 2]);
                }
                const bool diag = isText && (t == nK - 1);
#pragma unroll
                for (int tn = 0; tn < 8; tn++) {
#pragma unroll
                    for (int hf = 0; hf < 2; hf++) {
                        const int row = warp * 16 + grp + hf * 8;
                        const int col = j0 + tn * 8 + qd * 2;
                        float v0 = cs[tn][hf * 2 + 0];
                        float v1 = cs[tn][hf * 2 + 1];
                        if (diag) {
                            const int qglob = qtok0 + row;
                            if (col > qglob)     v0 = -1e30f;
                            if (col + 1 > qglob) v1 = -1e30f;
                        }
                        __half2 h = __floats2half2_rn(v0, v1);
                        *(unsigned*)sptr(sm + ATT_SOFF, row, col) = *(unsigned*)&h;
                    }
                }
            } else {
                float cs[4][4];
#pragma unroll
                for (int tn = 0; tn < 4; tn++)
#pragma unroll
                    for (int i = 0; i < 4; i++) cs[tn][i] = 0.f;
#pragma unroll
                for (int k16 = 0; k16 < 4; k16++) {
                    unsigned a[4], b[2][4];
                    ldsm4(a[0], a[1], a[2], a[3],
                          sb + ATT_QOFF + off16(aRow, k16 * 2 + aC));
#pragma unroll
                    for (int p = 0; p < 2; p++)
                        ldsm4(b[p][0], b[p][1], b[p][2], b[p][3],
                              kvb + off16(kb + p * 16 + bRow, k16 * 2 + bC));
#pragma unroll
                    for (int tn = 0; tn < 4; tn++)
                        mma_f16(cs[tn], a, &b[tn >> 1][(tn & 1) * 2]);
                }
#pragma unroll
                for (int tn = 0; tn < 4; tn++) {
#pragma unroll
                    for (int hf = 0; hf < 2; hf++) {
                        const int row = warp * 16 + grp + hf * 8;
                        const int qlocal = row & 31;
                        const int j = tn * 8 + qd * 2;
                        float v0 = (j     <= qlocal) ? cs[tn][hf * 2 + 0] : -1e30f;
                        float v1 = (j + 1 <= qlocal) ? cs[tn][hf * 2 + 1] : -1e30f;
                        __half2 h = __floats2half2_rn(v0, v1);
                        *(unsigned*)sptr(sm + ATT_SOFF, row, TXT + j) = *(unsigned*)&h;
                    }
                }
            }
        } else {
            const int v = t - nK;
            const bool imgTile = (!isText) && (v == 4);
            if (!imgTile) {
                const int j0 = v * 64;
#pragma unroll
                for (int k16 = 0; k16 < 4; k16++) {
                    unsigned a[4], b[4][4];
                    ldsm4(a[0], a[1], a[2], a[3],
                          sb + ATT_SOFF + sidx16(aRow, (j0 >> 3) + k16 * 2 + aC));
#pragma unroll
                    for (int n16 = 0; n16 < 4; n16++)
                        ldsm4t(b[n16][0], b[n16][1], b[n16][2], b[n16][3],
                               kvb + off16(k16 * 16 + (lane & 15),
                                           n16 * 2 + (lane >> 4)));
#pragma unroll
                    for (int tn = 0; tn < 8; tn++)
                        mma_f16(co[tn], a, &b[tn >> 1][(tn & 1) * 2]);
                }
            } else {
#pragma unroll
                for (int k16 = 0; k16 < 2; k16++) {
                    unsigned a[4], b[4][4];
                    ldsm4(a[0], a[1], a[2], a[3],
                          sb + ATT_SOFF + sidx16(aRow, (TXT >> 3) + k16 * 2 + aC));
#pragma unroll
                    for (int n16 = 0; n16 < 4; n16++)
                        ldsm4t(b[n16][0], b[n16][1], b[n16][2], b[n16][3],
                               kvb + off16(kb + k16 * 16 + (lane & 15),
                                           n16 * 2 + (lane >> 4)));
#pragma unroll
                    for (int tn = 0; tn < 8; tn++)
                        mma_f16(co[tn], a, &b[tn >> 1][(tn & 1) * 2]);
                }
            }
        }

        __syncthreads();
        if (t + 2 < total)
            att_cp_tile(sb + ((t & 1) ? ATT_B1 : ATT_B0), tile_src(t + 2), tid);
        cp_commit();
    }

    const float inv0 = invs[warp * 16 + grp];
    const float inv1 = invs[warp * 16 + grp + 8];
    const int b_ = bh >> 4, h_ = bh & 15;
#pragma unroll
    for (int tn = 0; tn < 8; tn++) {
#pragma unroll
        for (int hf = 0; hf < 2; hf++) {
            const int row = warp * 16 + grp + hf * 8;
            const int token = qtok0 + row;
            if (token >= NREAL) continue;
            const int m = b_ * NREAL + token;
            const int col = h_ * 64 + tn * 8 + qd * 2;
            const float inv = hf ? inv1 : inv0;
            __half2 h = __floats2half2_rn(co[tn][hf * 2 + 0] * inv,
                                          co[tn][hf * 2 + 1] * inv);
            *(unsigned*)(g_oh + (size_t)m * DIMn + col) = *(unsigned*)&h;
        }
    }
}

// ---------------------------------------------------------------------------
// Launch
// ---------------------------------------------------------------------------
extern "C" void kernel_launch(void* const* d_in, const int* in_sizes, int n_in,
                              void* d_out, int out_size)
{
    (void)in_sizes; (void)n_in; (void)out_size;
    const float* x     = (const float*)d_in[0];
    const float* w_qkv = (const float*)d_in[1];
    const float* w_out = (const float*)d_in[2];
    const float* b_out = (const float*)d_in[3];
    float* out = (float*)d_out;

    cudaFuncSetAttribute(attn_fused_kernel,
                         cudaFuncAttributeMaxDynamicSharedMemorySize, ATT_SMEM);
    cudaFuncSetAttribute(hgemm_kernel<0>,
                         cudaFuncAttributeMaxDynamicSharedMemorySize, HG_SMEM);
    cudaFuncSetAttribute(hgemm_kernel<1>,
                         cudaFuncAttributeMaxDynamicSharedMemorySize, HG_SMEM);

    void* p_xh;    cudaGetSymbolAddress(&p_xh, g_xh);
    void* p_wqkv;  cudaGetSymbolAddress(&p_wqkv, g_wqkvh);
    void* p_wout;  cudaGetSymbolAddress(&p_wout, g_wouth);
    void* p_oh;    cudaGetSymbolAddress(&p_oh, g_oh);

    // 0) fp32 -> fp16 conversions (single merged kernel)
    cvt_all_kernel<<<(CVT_TOT + 255) / 256, 256>>>(x, w_qkv, w_out);

    // 1) QKV projection: M=20480, N=3072 -> grid (12, 160)
    hgemm_kernel<0><<<dim3(12, 160), 256, HG_SMEM>>>(
        (const __half*)p_xh, (const __half*)p_wqkv, nullptr, nullptr, MQKV);

    // 2) fused text + axial image attention (pipelined tile loads)
    attn_fused_kernel<<<dim3(20, 256), 128, ATT_SMEM>>>();

    // 3) output projection: M=20464, N=1024 -> grid (4, 160)
    hgemm_kernel<1><<<dim3(4, 160), 256, HG_SMEM>>>(
        (const __half*)p_oh, (const __half*)p_wout, b_out, out, MOUT);
}

// round 10
// speedup vs baseline: 1.1950x; 1.1950x over previous
#include <cuda_runtime.h>
#include <cuda_fp16.h>
#include <float.h>

// ---------------------------------------------------------------------------
// Problem constants
// ---------------------------------------------------------------------------
#define Bn     16
#define Hn     16
#define DHn    64
#define NTOK   1280          // padded sequence (SEQ_LEN + 1)
#define NREAL  1279          // real tokens
#define DIMn   1024
#define TXT    256           // text length
#define BH     256           // Bn * Hn
#define HD     (NTOK * DHn)  // 81920 halfs per (b,h) plane
#define MQKV   (Bn * NTOK)   // 20480
#define MOUT   (Bn * NREAL)  // 20464
#define QSCALE 0.125f        // DH^-0.5

// ---------------------------------------------------------------------------
// Scratch (device globals: allocation-free)
// ---------------------------------------------------------------------------
__device__ __half g_qh[(size_t)BH * HD];
__device__ __half g_kh[(size_t)BH * HD];
__device__ __half g_vh[(size_t)BH * HD];
__device__ __half g_xh[(size_t)MQKV * DIMn];     // padded x in fp16
__device__ __half g_wqkvh[3 * DIMn * DIMn];      // w_qkv fp16
__device__ __half g_wouth[DIMn * DIMn];          // w_out fp16
__device__ __half g_oh[(size_t)MOUT * DIMn];     // attn out, de-interleaved fp16

// ---------------------------------------------------------------------------
// MMA / ldmatrix helpers
// ---------------------------------------------------------------------------
__device__ __forceinline__ void mma_f16(float c[4], const unsigned a[4],
                                        const unsigned b[2]) {
    asm volatile(
        "mma.sync.aligned.m16n8k16.row.col.f32.f16.f16.f32 "
        "{%0,%1,%2,%3}, {%4,%5,%6,%7}, {%8,%9}, {%0,%1,%2,%3};\n"
        : "+f"(c[0]), "+f"(c[1]), "+f"(c[2]), "+f"(c[3])
        : "r"(a[0]), "r"(a[1]), "r"(a[2]), "r"(a[3]), "r"(b[0]), "r"(b[1]));
}
__device__ __forceinline__ void ldsm4(unsigned& r0, unsigned& r1,
                                      unsigned& r2, unsigned& r3, unsigned addr) {
    asm volatile("ldmatrix.sync.aligned.m8n8.x4.shared.b16 {%0,%1,%2,%3}, [%4];\n"
                 : "=r"(r0), "=r"(r1), "=r"(r2), "=r"(r3) : "r"(addr));
}
__device__ __forceinline__ void ldsm4t(unsigned& r0, unsigned& r1,
                                       unsigned& r2, unsigned& r3, unsigned addr) {
    asm volatile("ldmatrix.sync.aligned.m8n8.x4.trans.shared.b16 {%0,%1,%2,%3}, [%4];\n"
                 : "=r"(r0), "=r"(r1), "=r"(r2), "=r"(r3) : "r"(addr));
}

// GEMM smem swizzle: 64B rows (32 halfs), chunk c (0..3)
__device__ __forceinline__ unsigned swz(int row, int c) {
    return (unsigned)(row * 64 + ((c ^ ((row >> 1) & 3)) << 4));
}
// Attention tiles: 128B rows (64 halfs), chunk c (0..7)
__device__ __forceinline__ unsigned off16(int row, int c) {
    return (unsigned)(row * 128 + ((c ^ (row & 7)) << 4));
}
// Score matrix S: 640B rows (320 halfs), chunk swizzle within 8-chunk groups
__device__ __forceinline__ unsigned sidx16(int row, int c) {
    int cc = (c & ~7) | ((c & 7) ^ (row & 7));
    return (unsigned)(row * 640 + (cc << 4));
}
__device__ __forceinline__ char* sptr(char* base, int row, int col) {
    return base + sidx16(row, col >> 3) + (col & 7) * 2;
}

__device__ __forceinline__ void cp16(unsigned dst, const void* src, bool v) {
    int sz = v ? 16 : 0;
    asm volatile("cp.async.cg.shared.global [%0], [%1], 16, %2;\n"
                 :: "r"(dst), "l"(src), "r"(sz) : "memory");
}
__device__ __forceinline__ void cp_commit() {
    asm volatile("cp.async.commit_group;\n" ::: "memory");
}
__device__ __forceinline__ void cp_wait2() {
    asm volatile("cp.async.wait_group 2;\n" ::: "memory");
}
__device__ __forceinline__ void cp_wait1() {
    asm volatile("cp.async.wait_group 1;\n" ::: "memory");
}

// ---------------------------------------------------------------------------
// fp16 HGEMM (exact R8/R6 version; QKV measured 390-392us, out-proj 139us).
// C[m,n] = sum_k A[m,k]*B[n,k]. 128x128x32 tile, 4-stage cp.async pipeline.
// EPI=0: scatter fp16 to g_qh/g_kh/g_vh head layout (Q scaled).
// EPI=1: fp32 out + bias.
// ---------------------------------------------------------------------------
template <int EPI>
__global__ __launch_bounds__(256, 2) void hgemm_kernel(
    const __half* __restrict__ A, const __half* __restrict__ B,
    const float* __restrict__ bias, float* __restrict__ out, int Mv)
{
    extern __shared__ __align__(16) __half gsm[];   // 4 stages x 16384 B
    const unsigned smbase = (unsigned)__cvta_generic_to_shared(gsm);

    const int tid = threadIdx.x;
    const int m0 = blockIdx.y * 128;
    const int n0 = blockIdx.x * 128;

    const int lr = tid >> 1;
    const int lc = (tid & 1) * 2;
    const __half* gA = A + (size_t)(m0 + lr) * DIMn + lc * 8;
    const __half* gB = B + (size_t)(n0 + lr) * DIMn + lc * 8;
    const bool av = (m0 + lr) < Mv;
    const unsigned dA0 = swz(lr, lc), dA1 = swz(lr, lc + 1);

    auto load_stage = [&](int s, int k0) {
        unsigned sb = smbase + s * 16384;
        const __half* pa = gA + k0;
        const __half* pb = gB + k0;
        cp16(sb + dA0, pa, av);
        cp16(sb + dA1, pa + 8, av);
        cp16(sb + 8192 + dA0, pb, true);
        cp16(sb + 8192 + dA1, pb + 8, true);
    };

    const int lane = tid & 31, warp = tid >> 5;
    const int wM = warp >> 1, wN = warp & 1;
    const int aRow = wM * 32 + (lane & 15);
    const int aCb  = lane >> 4;
    const int bRow = wN * 64 + (lane & 7) + ((lane >> 4) & 1) * 8;
    const int bCb  = (lane >> 3) & 1;

    float c[2][8][4];
#pragma unroll
    for (int tm = 0; tm < 2; tm++)
#pragma unroll
        for (int tn = 0; tn < 8; tn++)
#pragma unroll
            for (int i = 0; i < 4; i++) c[tm][tn][i] = 0.f;

    load_stage(0, 0);  cp_commit();
    load_stage(1, 32); cp_commit();
    load_stage(2, 64); cp_commit();

#pragma unroll 1
    for (int it = 0; it < 32; it++) {
        cp_wait2();
        __syncthreads();
        const unsigned sb = smbase + (it & 3) * 16384;

        unsigned a0[2][4], a1[2][4], b[4][4];
#pragma unroll
        for (int tm = 0; tm < 2; tm++) {
            ldsm4(a0[tm][0], a0[tm][1], a0[tm][2], a0[tm][3],
                  sb + swz(aRow + tm * 16, aCb));
            ldsm4(a1[tm][0], a1[tm][1], a1[tm][2], a1[tm][3],
                  sb + swz(aRow + tm * 16, aCb + 2));
        }
#pragma unroll
        for (int p = 0; p < 4; p++)
            ldsm4(b[p][0], b[p][1], b[p][2], b[p][3],
                  sb + 8192 + swz(bRow + p * 16, bCb));

        if (it + 3 < 32) load_stage((it + 3) & 3, (it + 3) * 32);
        cp_commit();

#pragma unroll
        for (int tm = 0; tm < 2; tm++)
#pragma unroll
            for (int tn = 0; tn < 8; tn++)
                mma_f16(c[tm][tn], a0[tm], &b[tn >> 1][(tn & 1) * 2]);

#pragma unroll
        for (int p = 0; p < 4; p++)
            ldsm4(b[p][0], b[p][1], b[p][2], b[p][3],
                  sb + 8192 + swz(bRow + p * 16, bCb + 2));
#pragma unroll
        for (int tm = 0; tm < 2; tm++)
#pragma unroll
            for (int tn = 0; tn < 8; tn++)
                mma_f16(c[tm][tn], a1[tm], &b[tn >> 1][(tn & 1) * 2]);
    }

    const int grp = lane >> 2, qd = lane & 3;
#pragma unroll
    for (int tm = 0; tm < 2; tm++) {
#pragma unroll
        for (int hf = 0; hf < 2; hf++) {
            const int mrow = m0 + wM * 32 + tm * 16 + grp + hf * 8;
            if (EPI == 0) {
                const int b_ = mrow / NTOK;
                const int n_ = mrow - b_ * NTOK;
#pragma unroll
                for (int tn = 0; tn < 8; tn++) {
                    const int col = n0 + wN * 64 + tn * 8 + qd * 2;
                    const int which = col >> 10;
                    const int cc = col & 1023;
                    const int h = cc >> 6;
                    const int d = cc & 63;
                    __half* dst = (which == 0) ? g_qh : ((which == 1) ? g_kh : g_vh);
                    const float sc = (which == 0) ? QSCALE : 1.0f;
                    __half2 hv = __floats2half2_rn(c[tm][tn][hf * 2 + 0] * sc,
                                                   c[tm][tn][hf * 2 + 1] * sc);
                    *(unsigned*)(dst + ((size_t)(b_ * Hn + h) * NTOK + n_) * DHn + d) =
                        *(unsigned*)&hv;
                }
            } else {
                if (mrow < Mv) {
#pragma unroll
                    for (int tn = 0; tn < 8; tn++) {
                        const int col = n0 + wN * 64 + tn * 8 + qd * 2;
                        float2 bb = *(const float2*)(bias + col);
                        float2 v;
                        v.x = c[tm][tn][hf * 2 + 0] + bb.x;
                        v.y = c[tm][tn][hf * 2 + 1] + bb.y;
                        *(float2*)(out + (size_t)mrow * DIMn + col) = v;
                    }
                }
            }
        }
    }
}

// ---------------------------------------------------------------------------
// Merged fp32 -> fp16 conversion kernel (x pad + w_qkv + w_out)
// ---------------------------------------------------------------------------
#define X_E4  (MQKV * DIMn / 4)
#define WQ_E4 (3 * DIMn * DIMn / 4)
#define WO_E4 (DIMn * DIMn / 4)
#define CVT_TOT (X_E4 + WQ_E4 + WO_E4)

__global__ __launch_bounds__(256) void cvt_all_kernel(
    const float* __restrict__ x, const float* __restrict__ wqkv,
    const float* __restrict__ wout)
{
    long i = (long)blockIdx.x * 256 + threadIdx.x;
    if (i >= CVT_TOT) return;
    float4 v;
    __half* dst;
    size_t e;
    if (i < X_E4) {
        e = (size_t)i * 4;
        int m = (int)(e >> 10);
        int col = (int)(e & 1023);
        int b = m / NTOK, n = m - b * NTOK;
        v = make_float4(0.f, 0.f, 0.f, 0.f);
        if (n < NREAL) v = *(const float4*)(x + ((size_t)b * NREAL + n) * DIMn + col);
        dst = g_xh;
    } else if (i < X_E4 + WQ_E4) {
        e = (size_t)(i - X_E4) * 4;
        v = *(const float4*)(wqkv + e);
        dst = g_wqkvh;
    } else {
        e = (size_t)(i - X_E4 - WQ_E4) * 4;
        v = *(const float4*)(wout + e);
        dst = g_wouth;
    }
    __half2 h0 = __floats2half2_rn(v.x, v.y);
    __half2 h1 = __floats2half2_rn(v.z, v.w);
    uint2 u;
    u.x = *(unsigned*)&h0;
    u.y = *(unsigned*)&h1;
    *(uint2*)(dst + e) = u;
}

// ---------------------------------------------------------------------------
// Fused tensor-core attention with cp.async ping-pong pipeline (R8) and
// VECTORIZED softmax: columns within a 16B swizzle chunk are contiguous, so
// the max/exp passes run on uint4 (8 halfs) instead of scalar LDS.16.
// smem: Q[64][64] @0, KVbuf0 @8192, KVbuf1 @16384, S[64][320] @24576,
//       inv[64] @65536. Total 65792 B -> 3 CTAs/SM.
// ---------------------------------------------------------------------------
#define ATT_QOFF 0
#define ATT_B0   8192
#define ATT_B1   16384
#define ATT_SOFF 24576
#define ATT_IOFF 65536
#define ATT_SMEM 65792

__device__ __forceinline__ void att_cp_tile(unsigned dstbase, const __half* g,
                                            int tid) {
#pragma unroll
    for (int r = 0; r < 4; r++) {
        int id = tid + 128 * r;
        int row = id >> 3, c = id & 7;
        cp16(dstbase + off16(row, c), g + row * 64 + c * 8, true);
    }
}

__global__ __launch_bounds__(128) void attn_fused_kernel()
{
    extern __shared__ char sm[];
    const unsigned sb = (unsigned)__cvta_generic_to_shared(sm);
    float* invs = (float*)(sm + ATT_IOFF);

    const int bh = blockIdx.y;
    const int bx = blockIdx.x;
    const bool isText = (bx < 4);
    const int tid = threadIdx.x, lane = tid & 31, warp = tid >> 5;
    const int grp = lane >> 2, qd = lane & 3;

    const int qtok0 = isText ? bx * 64 : TXT + (bx - 4) * 64;

    const __half* qg = g_qh + (size_t)bh * HD + (size_t)qtok0 * DHn;
    const __half* kg = g_kh + (size_t)bh * HD;
    const __half* vg = g_vh + (size_t)bh * HD;

    const int nK = isText ? (bx + 1) : 5;
    const int total = 2 * nK;
    const int ncols = isText ? (qtok0 + 64) : (TXT + 32);

    auto tile_src = [&](int t) -> const __half* {
        if (t < nK) {
            if (isText || t < 4) return kg + (size_t)t * 64 * DHn;
            return kg + (size_t)qtok0 * DHn;
        }
        int v = t - nK;
        if (isText || v < 4) return vg + (size_t)v * 64 * DHn;
        return vg + (size_t)qtok0 * DHn;
    };

    att_cp_tile(sb + ATT_QOFF, qg, tid);
    att_cp_tile(sb + ATT_B0, tile_src(0), tid);
    cp_commit();
    att_cp_tile(sb + ATT_B1, tile_src(1), tid);
    cp_commit();

    const int aRow = warp * 16 + (lane & 15);
    const int aC   = lane >> 4;
    const int bRow = (lane & 7) + ((lane >> 4) & 1) * 8;
    const int bC   = (lane >> 3) & 1;
    const int kb   = (warp >> 1) * 32;

    float co[8][4];
#pragma unroll
    for (int tn = 0; tn < 8; tn++)
#pragma unroll
        for (int i = 0; i < 4; i++) co[tn][i] = 0.f;

#pragma unroll 1
    for (int t = 0; t < total; t++) {
        cp_wait1();
        __syncthreads();

        if (t == nK) {
            // ---- vectorized softmax: 2 threads/row, uint4 chunks ----
            const int row = tid >> 1, hv = tid & 1;
            const int nch = ncols >> 4;          // chunks per half (8 cols/chunk)
            const int ch0 = hv * nch;
            char* srow = sm + ATT_SOFF;
            float mx = -FLT_MAX;
#pragma unroll 2
            for (int ch = ch0; ch < ch0 + nch; ch++) {
                uint4 v = *(uint4*)(srow + sidx16(row, ch));
                const __half2* hp = (const __half2*)&v;
#pragma unroll
                for (int i = 0; i < 4; i++) {
                    float2 f = __half22float2(hp[i]);
                    mx = fmaxf(mx, fmaxf(f.x, f.y));
                }
            }
            mx = fmaxf(mx, __shfl_xor_sync(0xffffffffu, mx, 1));
            float sum = 0.f;
#pragma unroll 2
            for (int ch = ch0; ch < ch0 + nch; ch++) {
                char* p = srow + sidx16(row, ch);
                uint4 v = *(uint4*)p;
                __half2* hp = (__half2*)&v;
#pragma unroll
                for (int i = 0; i < 4; i++) {
                    float2 f = __half22float2(hp[i]);
                    f.x = __expf(f.x - mx);
                    f.y = __expf(f.y - mx);
                    sum += f.x + f.y;
                    hp[i] = __floats2half2_rn(f.x, f.y);
                }
                *(uint4*)p = v;
            }
            sum += __shfl_xor_sync(0xffffffffu, sum, 1);
            if (hv == 0) invs[row] = 1.f / sum;
            __syncthreads();
        }

        const unsigned kvb = sb + ((t & 1) ? ATT_B1 : ATT_B0);

        if (t < nK) {
            const bool imgTile = (!isText) && (t == 4);
            if (!imgTile) {
                const int j0 = t * 64;
                float cs[8][4];
#pragma unroll
                for (int tn = 0; tn < 8; tn++)
#pragma unroll
                    for (int i = 0; i < 4; i++) cs[tn][i] = 0.f;
#pragma unroll
                for (int k16 = 0; k16 < 4; k16++) {
                    unsigned a[4], b[4][4];
                    ldsm4(a[0], a[1], a[2], a[3],
                          sb + ATT_QOFF + off16(aRow, k16 * 2 + aC));
#pragma unroll
                    for (int p = 0; p < 4; p++)
                        ldsm4(b[p][0], b[p][1], b[p][2], b[p][3],
                              kvb + off16(p * 16 + bRow, k16 * 2 + bC));
#pragma unroll
                    for (int tn = 0; tn < 8; tn++)
                        mma_f16(cs[tn], a, &b[tn >> 1][(tn & 1) * 2]);
                }
                const bool diag = isText && (t == nK - 1);
#pragma unroll
                for (int tn = 0; tn < 8; tn++) {
#pragma unroll
                    for (int hf = 0; hf < 2; hf++) {
                        const int row = warp * 16 + grp + hf * 8;
                        const int col = j0 + tn * 8 + qd * 2;
                        float v0 = cs[tn][hf * 2 + 0];
                        float v1 = cs[tn][hf * 2 + 1];
                        if (diag) {
                            const int qglob = qtok0 + row;
                            if (col > qglob)     v0 = -1e30f;
                            if (col + 1 > qglob) v1 = -1e30f;
                        }
                        __half2 h = __floats2half2_rn(v0, v1);
                        *(unsigned*)sptr(sm + ATT_SOFF, row, col) = *(unsigned*)&h;
                    }
                }
            } else {
                float cs[4][4];
#pragma unroll
                for (int tn = 0; tn < 4; tn++)
#pragma unroll
                    for (int i = 0; i < 4; i++) cs[tn][i] = 0.f;
#pragma unroll
                for (int k16 = 0; k16 < 4; k16++) {
                    unsigned a[4], b[2][4];
                    ldsm4(a[0], a[1], a[2], a[3],
                          sb + ATT_QOFF + off16(aRow, k16 * 2 + aC));
#pragma unroll
                    for (int p = 0; p < 2; p++)
                        ldsm4(b[p][0], b[p][1], b[p][2], b[p][3],
                              kvb + off16(kb + p * 16 + bRow, k16 * 2 + bC));
#pragma unroll
                    for (int tn = 0; tn < 4; tn++)
                        mma_f16(cs[tn], a, &b[tn >> 1][(tn & 1) * 2]);
                }
#pragma unroll
                for (int tn = 0; tn < 4; tn++) {
#pragma unroll
                    for (int hf = 0; hf < 2; hf++) {
                        const int row = warp * 16 + grp + hf * 8;
                        const int qlocal = row & 31;
                        const int j = tn * 8 + qd * 2;
                        float v0 = (j     <= qlocal) ? cs[tn][hf * 2 + 0] : -1e30f;
                        float v1 = (j + 1 <= qlocal) ? cs[tn][hf * 2 + 1] : -1e30f;
                        __half2 h = __floats2half2_rn(v0, v1);
                        *(unsigned*)sptr(sm + ATT_SOFF, row, TXT + j) = *(unsigned*)&h;
                    }
                }
            }
        } else {
            const int v = t - nK;
            const bool imgTile = (!isText) && (v == 4);
            if (!imgTile) {
                const int j0 = v * 64;
#pragma unroll
                for (int k16 = 0; k16 < 4; k16++) {
                    unsigned a[4], b[4][4];
                    ldsm4(a[0], a[1], a[2], a[3],
                          sb + ATT_SOFF + sidx16(aRow, (j0 >> 3) + k16 * 2 + aC));
#pragma unroll
                    for (int n16 = 0; n16 < 4; n16++)
                        ldsm4t(b[n16][0], b[n16][1], b[n16][2], b[n16][3],
                               kvb + off16(k16 * 16 + (lane & 15),
                                           n16 * 2 + (lane >> 4)));
#pragma unroll
                    for (int tn = 0; tn < 8; tn++)
                        mma_f16(co[tn], a, &b[tn >> 1][(tn & 1) * 2]);
                }
            } else {
#pragma unroll
                for (int k16 = 0; k16 < 2; k16++) {
                    unsigned a[4], b[4][4];
                    ldsm4(a[0], a[1], a[2], a[3],
                          sb + ATT_SOFF + sidx16(aRow, (TXT >> 3) + k16 * 2 + aC));
#pragma unroll
                    for (int n16 = 0; n16 < 4; n16++)
                        ldsm4t(b[n16][0], b[n16][1], b[n16][2], b[n16][3],
                               kvb + off16(kb + k16 * 16 + (lane & 15),
                                           n16 * 2 + (lane >> 4)));
#pragma unroll
                    for (int tn = 0; tn < 8; tn++)
                        mma_f16(co[tn], a, &b[tn >> 1][(tn & 1) * 2]);
                }
            }
        }

        __syncthreads();
        if (t + 2 < total)
            att_cp_tile(sb + ((t & 1) ? ATT_B1 : ATT_B0), tile_src(t + 2), tid);
        cp_commit();
    }

    const float inv0 = invs[warp * 16 + grp];
    const float inv1 = invs[warp * 16 + grp + 8];
    const int b_ = bh >> 4, h_ = bh & 15;
#pragma unroll
    for (int tn = 0; tn < 8; tn++) {
#pragma unroll
        for (int hf = 0; hf < 2; hf++) {
            const int row = warp * 16 + grp + hf * 8;
            const int token = qtok0 + row;
            if (token >= NREAL) continue;
            const int m = b_ * NREAL + token;
            const int col = h_ * 64 + tn * 8 + qd * 2;
            const float inv = hf ? inv1 : inv0;
            __half2 h = __floats2half2_rn(co[tn][hf * 2 + 0] * inv,
                                          co[tn][hf * 2 + 1] * inv);
            *(unsigned*)(g_oh + (size_t)m * DIMn + col) = *(unsigned*)&h;
        }
    }
}

// ---------------------------------------------------------------------------
// Launch
// ---------------------------------------------------------------------------
extern "C" void kernel_launch(void* const* d_in, const int* in_sizes, int n_in,
                              void* d_out, int out_size)
{
    (void)in_sizes; (void)n_in; (void)out_size;
    const float* x     = (const float*)d_in[0];
    const float* w_qkv = (const float*)d_in[1];
    const float* w_out = (const float*)d_in[2];
    const float* b_out = (const float*)d_in[3];
    float* out = (float*)d_out;

    cudaFuncSetAttribute(attn_fused_kernel,
                         cudaFuncAttributeMaxDynamicSharedMemorySize, ATT_SMEM);
    cudaFuncSetAttribute(hgemm_kernel<0>,
                         cudaFuncAttributeMaxDynamicSharedMemorySize, 65536);
    cudaFuncSetAttribute(hgemm_kernel<1>,
                         cudaFuncAttributeMaxDynamicSharedMemorySize, 65536);

    void* p_xh;    cudaGetSymbolAddress(&p_xh, g_xh);
    void* p_wqkv;  cudaGetSymbolAddress(&p_wqkv, g_wqkvh);
    void* p_wout;  cudaGetSymbolAddress(&p_wout, g_wouth);
    void* p_oh;    cudaGetSymbolAddress(&p_oh, g_oh);

    // 0) fp32 -> fp16 conversions (single merged kernel)
    cvt_all_kernel<<<(CVT_TOT + 255) / 256, 256>>>(x, w_qkv, w_out);

    // 1) QKV projection (fp16 tensor cores) into fp16 head-layout scratch
    hgemm_kernel<0><<<dim3(24, 160), 256, 65536>>>(
        (const __half*)p_xh, (const __half*)p_wqkv, nullptr, nullptr, MQKV);

    // 2) fused text + axial image attention (pipelined tile loads)
    attn_fused_kernel<<<dim3(20, 256), 128, ATT_SMEM>>>();

    // 3) output projection + bias (fp16 tensor cores)
    hgemm_kernel<1><<<dim3(8, 160), 256, 65536>>>(
        (const __half*)p_oh, (const __half*)p_wout, b_out, out, MOUT);
}

// round 11
// speedup vs baseline: 1.3228x; 1.1070x over previous
#include <cuda_runtime.h>
#include <cuda_fp16.h>
#include <float.h>

// ---------------------------------------------------------------------------
// Problem constants
// ---------------------------------------------------------------------------
#define Bn     16
#define Hn     16
#define DHn    64
#define NTOK   1280          // padded sequence (SEQ_LEN + 1)
#define NREAL  1279          // real tokens
#define DIMn   1024
#define TXT    256           // text length
#define BH     256           // Bn * Hn
#define HD     (NTOK * DHn)  // 81920 halfs per (b,h) plane
#define MQKV   (Bn * NTOK)   // 20480
#define MOUT   (Bn * NREAL)  // 20464
#define QSCALE 0.125f        // DH^-0.5

// ---------------------------------------------------------------------------
// Scratch (device globals: allocation-free)
// ---------------------------------------------------------------------------
__device__ __half g_qh[(size_t)BH * HD];
__device__ __half g_kh[(size_t)BH * HD];
__device__ __half g_vh[(size_t)BH * HD];
__device__ __half g_xh[(size_t)MQKV * DIMn];     // padded x in fp16
__device__ __half g_wqkvh[3 * DIMn * DIMn];      // w_qkv fp16
__device__ __half g_wouth[DIMn * DIMn];          // w_out fp16
__device__ __half g_oh[(size_t)MOUT * DIMn];     // attn out, de-interleaved fp16

// ---------------------------------------------------------------------------
// MMA / ldmatrix helpers
// ---------------------------------------------------------------------------
__device__ __forceinline__ void mma_f16(float c[4], const unsigned a[4],
                                        const unsigned b[2]) {
    asm volatile(
        "mma.sync.aligned.m16n8k16.row.col.f32.f16.f16.f32 "
        "{%0,%1,%2,%3}, {%4,%5,%6,%7}, {%8,%9}, {%0,%1,%2,%3};\n"
        : "+f"(c[0]), "+f"(c[1]), "+f"(c[2]), "+f"(c[3])
        : "r"(a[0]), "r"(a[1]), "r"(a[2]), "r"(a[3]), "r"(b[0]), "r"(b[1]));
}
__device__ __forceinline__ void ldsm4(unsigned& r0, unsigned& r1,
                                      unsigned& r2, unsigned& r3, unsigned addr) {
    asm volatile("ldmatrix.sync.aligned.m8n8.x4.shared.b16 {%0,%1,%2,%3}, [%4];\n"
                 : "=r"(r0), "=r"(r1), "=r"(r2), "=r"(r3) : "r"(addr));
}
__device__ __forceinline__ void ldsm4t(unsigned& r0, unsigned& r1,
                                       unsigned& r2, unsigned& r3, unsigned addr) {
    asm volatile("ldmatrix.sync.aligned.m8n8.x4.trans.shared.b16 {%0,%1,%2,%3}, [%4];\n"
                 : "=r"(r0), "=r"(r1), "=r"(r2), "=r"(r3) : "r"(addr));
}

// Attention/GEMM tiles: 128B rows (64 halfs), chunk c (0..7)
__device__ __forceinline__ unsigned off16(int row, int c) {
    return (unsigned)(row * 128 + ((c ^ (row & 7)) << 4));
}
// Score matrix S: 640B rows (320 halfs), chunk swizzle within 8-chunk groups
__device__ __forceinline__ unsigned sidx16(int row, int c) {
    int cc = (c & ~7) | ((c & 7) ^ (row & 7));
    return (unsigned)(row * 640 + (cc << 4));
}
__device__ __forceinline__ char* sptr(char* base, int row, int col) {
    return base + sidx16(row, col >> 3) + (col & 7) * 2;
}

__device__ __forceinline__ void cp16(unsigned dst, const void* src, bool v) {
    int sz = v ? 16 : 0;
    asm volatile("cp.async.cg.shared.global [%0], [%1], 16, %2;\n"
                 :: "r"(dst), "l"(src), "r"(sz) : "memory");
}
__device__ __forceinline__ void cp_commit() {
    asm volatile("cp.async.commit_group;\n" ::: "memory");
}
__device__ __forceinline__ void cp_wait1() {
    asm volatile("cp.async.wait_group 1;\n" ::: "memory");
}

// ---------------------------------------------------------------------------
// fp16 HGEMM v2: 128x128 CTA tile, BK=64 per sync, 3-stage cp.async pipeline
// (96KB dyn smem, 2 CTAs/SM), fragments single-buffered across 4 k16 steps.
// Smem-staged coalesced epilogues.
// EPI=0: fp16 to g_qh/g_kh/g_vh head layout (block-constant which/scale).
// EPI=1: fp32 out + bias.
// Stage layout: A 128x64h swizzled (16KB) @ +0, B same @ +16384.
// ---------------------------------------------------------------------------
#define HG_STG  32768
#define HG_SMEM (3 * HG_STG)   // 98304

template <int EPI>
__global__ __launch_bounds__(256, 2) void hgemm_kernel(
    const __half* __restrict__ A, const __half* __restrict__ B,
    const float* __restrict__ bias, float* __restrict__ out, int Mv)
{
    extern __shared__ __align__(16) __half gsm[];
    const unsigned smbase = (unsigned)__cvta_generic_to_shared(gsm);

    const int tid = threadIdx.x;
    const int m0 = blockIdx.y * 128;
    const int n0 = blockIdx.x * 128;

    auto load_stage = [&](int s, int kc) {
        const unsigned sa = smbase + s * HG_STG;
        const int kofs = kc * 64;
#pragma unroll
        for (int r = 0; r < 4; r++) {
            const int id = tid + 256 * r;
            const int row = id >> 3, c = id & 7;
            cp16(sa + off16(row, c),
                 A + (size_t)(m0 + row) * DIMn + kofs + c * 8, (m0 + row) < Mv);
        }
#pragma unroll
        for (int r = 0; r < 4; r++) {
            const int id = tid + 256 * r;
            const int row = id >> 3, c = id & 7;
            cp16(sa + 16384 + off16(row, c),
                 B + (size_t)(n0 + row) * DIMn + kofs + c * 8, true);
        }
    };

    const int lane = tid & 31, warp = tid >> 5;
    const int wM = warp >> 1, wN = warp & 1;         // 4 x 2 warps, 32x64 tile
    const int aRow = wM * 32 + (lane & 15);
    const int aC   = lane >> 4;
    const int bRow = wN * 64 + (lane & 7) + ((lane >> 4) & 1) * 8;
    const int bC   = (lane >> 3) & 1;

    float c[2][8][4];
#pragma unroll
    for (int tm = 0; tm < 2; tm++)
#pragma unroll
        for (int tn = 0; tn < 8; tn++)
#pragma unroll
            for (int i = 0; i < 4; i++) c[tm][tn][i] = 0.f;

    load_stage(0, 0); cp_commit();
    load_stage(1, 1); cp_commit();

#pragma unroll 1
    for (int it = 0; it < 16; it++) {
        cp_wait1();
        __syncthreads();
        const int s = it - (it / 3) * 3;
        const unsigned sa = smbase + s * HG_STG;
        const unsigned sbB = sa + 16384;

#pragma unroll
        for (int k16 = 0; k16 < 4; k16++) {
            unsigned a[2][4], b[4][4];
#pragma unroll
            for (int tm = 0; tm < 2; tm++)
                ldsm4(a[tm][0], a[tm][1], a[tm][2], a[tm][3],
                      sa + off16(aRow + tm * 16, k16 * 2 + aC));
#pragma unroll
            for (int p = 0; p < 4; p++)
                ldsm4(b[p][0], b[p][1], b[p][2], b[p][3],
                      sbB + off16(bRow + p * 16, k16 * 2 + bC));
#pragma unroll
            for (int tm = 0; tm < 2; tm++)
#pragma unroll
                for (int tn = 0; tn < 8; tn++)
                    mma_f16(c[tm][tn], a[tm], &b[tn >> 1][(tn & 1) * 2]);
            if (k16 == 0 && it + 2 < 16) load_stage((it + 2) % 3, it + 2);
        }
        cp_commit();     // one group per iteration (may be empty near tail)
    }

    const int grp = lane >> 2, qd = lane & 3;
    __syncthreads();     // pipeline done; smem becomes epilogue staging

    if (EPI == 0) {
        // which/scale are block-constant (n0 is a multiple of 128)
        const int which = n0 >> 10;
        __half* dst = (which == 0) ? g_qh : ((which == 1) ? g_kh : g_vh);
        const float sc = (which == 0) ? QSCALE : 1.0f;
        __half* st = gsm;                 // 128 x 136 halfs (34816 B)
#pragma unroll
        for (int tm = 0; tm < 2; tm++)
#pragma unroll
            for (int hf = 0; hf < 2; hf++) {
                const int row = wM * 32 + tm * 16 + grp + hf * 8;
#pragma unroll
                for (int tn = 0; tn < 8; tn++) {
                    const int col = wN * 64 + tn * 8 + qd * 2;
                    __half2 hv = __floats2half2_rn(c[tm][tn][hf * 2 + 0] * sc,
                                                   c[tm][tn][hf * 2 + 1] * sc);
                    *(__half2*)(st + row * 136 + col) = hv;
                }
            }
        __syncthreads();
        const int r = tid >> 1, seg = tid & 1;
        const int mrow = m0 + r;
        if (mrow < Mv) {
            const int gcol = n0 + seg * 64;
            const int h = (gcol & 1023) >> 6;
            const int b_ = mrow / NTOK;
            const int n_ = mrow - b_ * NTOK;
            __half* base = dst + ((size_t)(b_ * Hn + h) * NTOK + n_) * DHn;
            const __half* src = st + r * 136 + seg * 64;
#pragma unroll
            for (int i = 0; i < 8; i++)
                *(uint4*)(base + i * 8) = *(const uint4*)(src + i * 8);
        }
    } else {
        float* st = (float*)gsm;          // 128 x 136 floats (69632 B)
#pragma unroll
        for (int tm = 0; tm < 2; tm++)
#pragma unroll
            for (int hf = 0; hf < 2; hf++) {
                const int row = wM * 32 + tm * 16 + grp + hf * 8;
#pragma unroll
                for (int tn = 0; tn < 8; tn++) {
                    const int col = wN * 64 + tn * 8 + qd * 2;
                    float2 v = make_float2(c[tm][tn][hf * 2 + 0],
                                           c[tm][tn][hf * 2 + 1]);
                    *(float2*)(st + row * 136 + col) = v;
                }
            }
        __syncthreads();
        const int r = tid >> 1, seg = tid & 1;
        const int mrow = m0 + r;
        if (mrow < Mv) {
            const float* src = st + r * 136 + seg * 64;
            const float* bsrc = bias + n0 + seg * 64;
            float* dstp = out + (size_t)mrow * DIMn + n0 + seg * 64;
#pragma unroll
            for (int i = 0; i < 16; i++) {
                float4 v = *(const float4*)(src + i * 4);
                float4 bb = *(const float4*)(bsrc + i * 4);
                v.x += bb.x; v.y += bb.y; v.z += bb.z; v.w += bb.w;
                *(float4*)(dstp + i * 4) = v;
            }
        }
    }
}

// ---------------------------------------------------------------------------
// Merged fp32 -> fp16 conversion kernel (x pad + w_qkv + w_out)
// ---------------------------------------------------------------------------
#define X_E4  (MQKV * DIMn / 4)
#define WQ_E4 (3 * DIMn * DIMn / 4)
#define WO_E4 (DIMn * DIMn / 4)
#define CVT_TOT (X_E4 + WQ_E4 + WO_E4)

__global__ __launch_bounds__(256) void cvt_all_kernel(
    const float* __restrict__ x, const float* __restrict__ wqkv,
    const float* __restrict__ wout)
{
    long i = (long)blockIdx.x * 256 + threadIdx.x;
    if (i >= CVT_TOT) return;
    float4 v;
    __half* dst;
    size_t e;
    if (i < X_E4) {
        e = (size_t)i * 4;
        int m = (int)(e >> 10);
        int col = (int)(e & 1023);
        int b = m / NTOK, n = m - b * NTOK;
        v = make_float4(0.f, 0.f, 0.f, 0.f);
        if (n < NREAL) v = *(const float4*)(x + ((size_t)b * NREAL + n) * DIMn + col);
        dst = g_xh;
    } else if (i < X_E4 + WQ_E4) {
        e = (size_t)(i - X_E4) * 4;
        v = *(const float4*)(wqkv + e);
        dst = g_wqkvh;
    } else {
        e = (size_t)(i - X_E4 - WQ_E4) * 4;
        v = *(const float4*)(wout + e);
        dst = g_wouth;
    }
    __half2 h0 = __floats2half2_rn(v.x, v.y);
    __half2 h1 = __floats2half2_rn(v.z, v.w);
    uint2 u;
    u.x = *(unsigned*)&h0;
    u.y = *(unsigned*)&h1;
    *(uint2*)(dst + e) = u;
}

// ---------------------------------------------------------------------------
// Fused tensor-core attention: cp.async ping-pong pipeline, vectorized
// softmax (R10), and NEW smem-staged coalesced output.
// smem: Q[64][64] @0, KVbuf0 @8192, KVbuf1 @16384, S[64][320] @24576,
//       inv[64] @65536. Total 65792 B -> 3 CTAs/SM.
// ---------------------------------------------------------------------------
#define ATT_QOFF 0
#define ATT_B0   8192
#define ATT_B1   16384
#define ATT_SOFF 24576
#define ATT_IOFF 65536
#define ATT_SMEM 65792

__device__ __forceinline__ void att_cp_tile(unsigned dstbase, const __half* g,
                                            int tid) {
#pragma unroll
    for (int r = 0; r < 4; r++) {
        int id = tid + 128 * r;
        int row = id >> 3, c = id & 7;
        cp16(dstbase + off16(row, c), g + row * 64 + c * 8, true);
    }
}

__global__ __launch_bounds__(128) void attn_fused_kernel()
{
    extern __shared__ char sm[];
    const unsigned sb = (unsigned)__cvta_generic_to_shared(sm);
    float* invs = (float*)(sm + ATT_IOFF);

    const int bh = blockIdx.y;
    const int bx = blockIdx.x;
    const bool isText = (bx < 4);
    const int tid = threadIdx.x, lane = tid & 31, warp = tid >> 5;
    const int grp = lane >> 2, qd = lane & 3;

    const int qtok0 = isText ? bx * 64 : TXT + (bx - 4) * 64;

    const __half* qg = g_qh + (size_t)bh * HD + (size_t)qtok0 * DHn;
    const __half* kg = g_kh + (size_t)bh * HD;
    const __half* vg = g_vh + (size_t)bh * HD;

    const int nK = isText ? (bx + 1) : 5;
    const int total = 2 * nK;
    const int ncols = isText ? (qtok0 + 64) : (TXT + 32);

    auto tile_src = [&](int t) -> const __half* {
        if (t < nK) {
            if (isText || t < 4) return kg + (size_t)t * 64 * DHn;
            return kg + (size_t)qtok0 * DHn;
        }
        int v = t - nK;
        if (isText || v < 4) return vg + (size_t)v * 64 * DHn;
        return vg + (size_t)qtok0 * DHn;
    };

    att_cp_tile(sb + ATT_QOFF, qg, tid);
    att_cp_tile(sb + ATT_B0, tile_src(0), tid);
    cp_commit();
    att_cp_tile(sb + ATT_B1, tile_src(1), tid);
    cp_commit();

    const int aRow = warp * 16 + (lane & 15);
    const int aC   = lane >> 4;
    const int bRow = (lane & 7) + ((lane >> 4) & 1) * 8;
    const int bC   = (lane >> 3) & 1;
    const int kb   = (warp >> 1) * 32;

    float co[8][4];
#pragma unroll
    for (int tn = 0; tn < 8; tn++)
#pragma unroll
        for (int i = 0; i < 4; i++) co[tn][i] = 0.f;

#pragma unroll 1
    for (int t = 0; t < total; t++) {
        cp_wait1();
        __syncthreads();

        if (t == nK) {
            // ---- vectorized softmax: 2 threads/row, uint4 chunks ----
            const int row = tid >> 1, hv = tid & 1;
            const int nch = ncols >> 4;
            const int ch0 = hv * nch;
            char* srow = sm + ATT_SOFF;
            float mx = -FLT_MAX;
#pragma unroll 2
            for (int ch = ch0; ch < ch0 + nch; ch++) {
                uint4 v = *(uint4*)(srow + sidx16(row, ch));
                const __half2* hp = (const __half2*)&v;
#pragma unroll
                for (int i = 0; i < 4; i++) {
                    float2 f = __half22float2(hp[i]);
                    mx = fmaxf(mx, fmaxf(f.x, f.y));
                }
            }
            mx = fmaxf(mx, __shfl_xor_sync(0xffffffffu, mx, 1));
            float sum = 0.f;
#pragma unroll 2
            for (int ch = ch0; ch < ch0 + nch; ch++) {
                char* p = srow + sidx16(row, ch);
                uint4 v = *(uint4*)p;
                __half2* hp = (__half2*)&v;
#pragma unroll
                for (int i = 0; i < 4; i++) {
                    float2 f = __half22float2(hp[i]);
                    f.x = __expf(f.x - mx);
                    f.y = __expf(f.y - mx);
                    sum += f.x + f.y;
                    hp[i] = __floats2half2_rn(f.x, f.y);
                }
                *(uint4*)p = v;
            }
            sum += __shfl_xor_sync(0xffffffffu, sum, 1);
            if (hv == 0) invs[row] = 1.f / sum;
            __syncthreads();
        }

        const unsigned kvb = sb + ((t & 1) ? ATT_B1 : ATT_B0);

        if (t < nK) {
            const bool imgTile = (!isText) && (t == 4);
            if (!imgTile) {
                const int j0 = t * 64;
                float cs[8][4];
#pragma unroll
                for (int tn = 0; tn < 8; tn++)
#pragma unroll
                    for (int i = 0; i < 4; i++) cs[tn][i] = 0.f;
#pragma unroll
                for (int k16 = 0; k16 < 4; k16++) {
                    unsigned a[4], b[4][4];
                    ldsm4(a[0], a[1], a[2], a[3],
                          sb + ATT_QOFF + off16(aRow, k16 * 2 + aC));
#pragma unroll
                    for (int p = 0; p < 4; p++)
                        ldsm4(b[p][0], b[p][1], b[p][2], b[p][3],
                              kvb + off16(p * 16 + bRow, k16 * 2 + bC));
#pragma unroll
                    for (int tn = 0; tn < 8; tn++)
                        mma_f16(cs[tn], a, &b[tn >> 1][(tn & 1) * 2]);
                }
                const bool diag = isText && (t == nK - 1);
#pragma unroll
                for (int tn = 0; tn < 8; tn++) {
#pragma unroll
                    for (int hf = 0; hf < 2; hf++) {
                        const int row = warp * 16 + grp + hf * 8;
                        const int col = j0 + tn * 8 + qd * 2;
                        float v0 = cs[tn][hf * 2 + 0];
                        float v1 = cs[tn][hf * 2 + 1];
                        if (diag) {
                            const int qglob = qtok0 + row;
                            if (col > qglob)     v0 = -1e30f;
                            if (col + 1 > qglob) v1 = -1e30f;
                        }
                        __half2 h = __floats2half2_rn(v0, v1);
                        *(unsigned*)sptr(sm + ATT_SOFF, row, col) = *(unsigned*)&h;
                    }
                }
            } else {
                float cs[4][4];
#pragma unroll
                for (int tn = 0; tn < 4; tn++)
#pragma unroll
                    for (int i = 0; i < 4; i++) cs[tn][i] = 0.f;
#pragma unroll
                for (int k16 = 0; k16 < 4; k16++) {
                    unsigned a[4], b[2][4];
                    ldsm4(a[0], a[1], a[2], a[3],
                          sb + ATT_QOFF + off16(aRow, k16 * 2 + aC));
#pragma unroll
                    for (int p = 0; p < 2; p++)
                        ldsm4(b[p][0], b[p][1], b[p][2], b[p][3],
                              kvb + off16(kb + p * 16 + bRow, k16 * 2 + bC));
#pragma unroll
                    for (int tn = 0; tn < 4; tn++)
                        mma_f16(cs[tn], a, &b[tn >> 1][(tn & 1) * 2]);
                }
#pragma unroll
                for (int tn = 0; tn < 4; tn++) {
#pragma unroll
                    for (int hf = 0; hf < 2; hf++) {
                        const int row = warp * 16 + grp + hf * 8;
                        const int qlocal = row & 31;
                        const int j = tn * 8 + qd * 2;
                        float v0 = (j     <= qlocal) ? cs[tn][hf * 2 + 0] : -1e30f;
                        float v1 = (j + 1 <= qlocal) ? cs[tn][hf * 2 + 1] : -1e30f;
                        __half2 h = __floats2half2_rn(v0, v1);
                        *(unsigned*)sptr(sm + ATT_SOFF, row, TXT + j) = *(unsigned*)&h;
                    }
                }
            }
        } else {
            const int v = t - nK;
            const bool imgTile = (!isText) && (v == 4);
            if (!imgTile) {
                const int j0 = v * 64;
#pragma unroll
                for (int k16 = 0; k16 < 4; k16++) {
                    unsigned a[4], b[4][4];
                    ldsm4(a[0], a[1], a[2], a[3],
                          sb + ATT_SOFF + sidx16(aRow, (j0 >> 3) + k16 * 2 + aC));
#pragma unroll
                    for (int n16 = 0; n16 < 4; n16++)
                        ldsm4t(b[n16][0], b[n16][1], b[n16][2], b[n16][3],
                               kvb + off16(k16 * 16 + (lane & 15),
                                           n16 * 2 + (lane >> 4)));
#pragma unroll
                    for (int tn = 0; tn < 8; tn++)
                        mma_f16(co[tn], a, &b[tn >> 1][(tn & 1) * 2]);
                }
            } else {
#pragma unroll
                for (int k16 = 0; k16 < 2; k16++) {
                    unsigned a[4], b[4][4];
                    ldsm4(a[0], a[1], a[2], a[3],
                          sb + ATT_SOFF + sidx16(aRow, (TXT >> 3) + k16 * 2 + aC));
#pragma unroll
                    for (int n16 = 0; n16 < 4; n16++)
                        ldsm4t(b[n16][0], b[n16][1], b[n16][2], b[n16][3],
                               kvb + off16(kb + k16 * 16 + (lane & 15),
                                           n16 * 2 + (lane >> 4)));
#pragma unroll
                    for (int tn = 0; tn < 8; tn++)
                        mma_f16(co[tn], a, &b[tn >> 1][(tn & 1) * 2]);
                }
            }
        }

        __syncthreads();
        if (t + 2 < total)
            att_cp_tile(sb + ((t & 1) ? ATT_B1 : ATT_B0), tile_src(t + 2), tid);
        cp_commit();
    }

    // ---- output: stage (co * inv) into S region, then coalesced stores ----
    const float inv0 = invs[warp * 16 + grp];
    const float inv1 = invs[warp * 16 + grp + 8];
    __half* st = (__half*)(sm + ATT_SOFF);    // 64 x 72 halfs
#pragma unroll
    for (int tn = 0; tn < 8; tn++) {
#pragma unroll
        for (int hf = 0; hf < 2; hf++) {
            const int row = warp * 16 + grp + hf * 8;
            const int col = tn * 8 + qd * 2;
            const float inv = hf ? inv1 : inv0;
            __half2 h = __floats2half2_rn(co[tn][hf * 2 + 0] * inv,
                                          co[tn][hf * 2 + 1] * inv);
            *(__half2*)(st + row * 72 + col) = h;
        }
    }
    __syncthreads();
    {
        const int row = tid >> 1, seg = tid & 1;
        const int token = qtok0 + row;
        if (token < NREAL) {
            const int b_ = bh >> 4, h_ = bh & 15;
            const int m = b_ * NREAL + token;
            __half* dstp = g_oh + (size_t)m * DIMn + h_ * 64 + seg * 32;
            const __half* srcp = st + row * 72 + seg * 32;
#pragma unroll
            for (int i = 0; i < 4; i++)
                *(uint4*)(dstp + i * 8) = *(const uint4*)(srcp + i * 8);
        }
    }
}

// ---------------------------------------------------------------------------
// Launch
// ---------------------------------------------------------------------------
extern "C" void kernel_launch(void* const* d_in, const int* in_sizes, int n_in,
                              void* d_out, int out_size)
{
    (void)in_sizes; (void)n_in; (void)out_size;
    const float* x     = (const float*)d_in[0];
    const float* w_qkv = (const float*)d_in[1];
    const float* w_out = (const float*)d_in[2];
    const float* b_out = (const float*)d_in[3];
    float* out = (float*)d_out;

    cudaFuncSetAttribute(attn_fused_kernel,
                         cudaFuncAttributeMaxDynamicSharedMemorySize, ATT_SMEM);
    cudaFuncSetAttribute(hgemm_kernel<0>,
                         cudaFuncAttributeMaxDynamicSharedMemorySize, HG_SMEM);
    cudaFuncSetAttribute(hgemm_kernel<1>,
                         cudaFuncAttributeMaxDynamicSharedMemorySize, HG_SMEM);

    void* p_xh;    cudaGetSymbolAddress(&p_xh, g_xh);
    void* p_wqkv;  cudaGetSymbolAddress(&p_wqkv, g_wqkvh);
    void* p_wout;  cudaGetSymbolAddress(&p_wout, g_wouth);
    void* p_oh;    cudaGetSymbolAddress(&p_oh, g_oh);

    // 0) fp32 -> fp16 conversions (single merged kernel)
    cvt_all_kernel<<<(CVT_TOT + 255) / 256, 256>>>(x, w_qkv, w_out);

    // 1) QKV projection (fp16 tensor cores) into fp16 head-layout scratch
    hgemm_kernel<0><<<dim3(24, 160), 256, HG_SMEM>>>(
        (const __half*)p_xh, (const __half*)p_wqkv, nullptr, nullptr, MQKV);

    // 2) fused text + axial image attention (pipelined tile loads)
    attn_fused_kernel<<<dim3(20, 256), 128, ATT_SMEM>>>();

    // 3) output projection + bias (fp16 tensor cores)
    hgemm_kernel<1><<<dim3(8, 160), 256, HG_SMEM>>>(
        (const __half*)p_oh, (const __half*)p_wout, b_out, out, MOUT);
}